// round 14
// baseline (speedup 1.0000x reference)
#include <cuda_runtime.h>
#include <cuda_fp16.h>
#include <cstdint>

#define T_TOKENS 4096
#define DM 512
#define NE 8
#define DF 2048
#define NPAIRS (T_TOKENS * 2)
#define CAP 8192      // fixed per-expert segment capacity
#define MAXTILE 72    // grid upper bound for M=128 tiles

// ---------------- device scratch ------------------------------------------
__device__ int   g_ctrl[NE];                      // per-expert pair counts
__device__ int   g_row_tok[NE * CAP];
__device__ float g_row_gate[NE * CAP];
__device__ __half g_xg[(size_t)NE * CAP * DM];    // 64 MiB fixed-base gathered x
__device__ __half g_Y1[(size_t)NE * CAP * DF];    // 256 MiB fixed-base Y1
__device__ __half g_W1h[(size_t)NE * DM * DF];    // 16 MiB
__device__ __half g_W2h[(size_t)NE * DF * DM];    // 16 MiB

// ---------------- helpers ----------------------------------------------------
#define LDSM_X4(R, ADDR) \
    asm volatile("ldmatrix.sync.aligned.m8n8.x4.shared.b16 {%0,%1,%2,%3}, [%4];" \
        : "=r"((R)[0]), "=r"((R)[1]), "=r"((R)[2]), "=r"((R)[3]) : "r"(ADDR))

#define LDSM_X4T(R0, R1, R2, R3, ADDR) \
    asm volatile("ldmatrix.sync.aligned.m8n8.x4.trans.shared.b16 {%0,%1,%2,%3}, [%4];" \
        : "=r"(R0), "=r"(R1), "=r"(R2), "=r"(R3) : "r"(ADDR))

#define MMA_F16(C, A, B) \
    asm volatile("mma.sync.aligned.m16n8k16.row.col.f32.f16.f16.f32 " \
        "{%0,%1,%2,%3}, {%4,%5,%6,%7}, {%8,%9}, {%0,%1,%2,%3};" \
        : "+f"((C)[0]), "+f"((C)[1]), "+f"((C)[2]), "+f"((C)[3]) \
        : "r"((A)[0]), "r"((A)[1]), "r"((A)[2]), "r"((A)[3]), \
          "r"((B)[0]), "r"((B)[1]))

#define CP16(DST, SRC) \
    asm volatile("cp.async.cg.shared.global [%0], [%1], 16;" \
        :: "r"(DST), "l"(SRC))
#define CP_COMMIT() asm volatile("cp.async.commit_group;")
#define CP_WAIT(N)  asm volatile("cp.async.wait_group %0;" :: "n"(N))

__device__ __forceinline__ void cvt4(const float* srcp, __half* dst) {
    float4 v = *reinterpret_cast<const float4*>(srcp);
    __half2 a = __floats2half2_rn(v.x, v.y);
    __half2 b = __floats2half2_rn(v.z, v.w);
    uint2 o;
    o.x = *reinterpret_cast<uint32_t*>(&a);
    o.y = *reinterpret_cast<uint32_t*>(&b);
    *reinterpret_cast<uint2*>(dst) = o;
}

// locate M=128 tile for linear tile id bx; returns false if beyond last tile
__device__ __forceinline__ bool tile_lookup(int bx, int& e, int& m0) {
#pragma unroll
    for (int ee = 0; ee < NE; ee++) {
        int nt = (g_ctrl[ee] + 127) >> 7;
        if (bx < nt) { e = ee; m0 = bx << 7; return true; }
        bx -= nt;
    }
    return false;
}

// ---------------- gate+slot+gather (blocks 0..511) + W1 convert (rest) ------
#define GATE_BLKS 512
#define CVT1_BLKS ((NE * DM * DF / 4) / 256)       // 8192

__global__ __launch_bounds__(256)
void gatecvt_kernel(const float* __restrict__ x,
                    const float* __restrict__ Wg,
                    const float* __restrict__ bg,
                    const float* __restrict__ W1,
                    float* __restrict__ out) {
    const int bid = blockIdx.x;
    if (bid >= GATE_BLKS) {
        int idx = (bid - GATE_BLKS) * 256 + threadIdx.x;
        cvt4(W1 + (size_t)idx * 4, g_W1h + (size_t)idx * 4);
        return;
    }

    // zero this block's 8 output token rows (1024 float4)
    {
        float4 z; z.x = z.y = z.z = z.w = 0.0f;
        float4* ob = reinterpret_cast<float4*>(out) + (size_t)bid * 1024;
#pragma unroll
        for (int i = 0; i < 4; i++) ob[threadIdx.x + 256 * i] = z;
    }

    __shared__ float sWgT[NE * DM];   // transposed [e][d]
    for (int i = threadIdx.x; i < DM * NE; i += blockDim.x) {
        int d = i >> 3, e = i & 7;
        sWgT[e * DM + d] = Wg[i];
    }
    __syncthreads();

    int warp = threadIdx.x >> 5, lane = threadIdx.x & 31;
    int t = bid * 8 + warp;
    const float* xr = x + (size_t)t * DM;

    float lg[NE];
#pragma unroll
    for (int e = 0; e < NE; e++) lg[e] = 0.0f;
#pragma unroll
    for (int i = 0; i < DM / 32; i++) {
        int d = lane + 32 * i;
        float xv = xr[d];
#pragma unroll
        for (int e = 0; e < NE; e++)
            lg[e] = fmaf(xv, sWgT[e * DM + d], lg[e]);
    }
#pragma unroll
    for (int off = 16; off > 0; off >>= 1)
#pragma unroll
        for (int e = 0; e < NE; e++)
            lg[e] += __shfl_xor_sync(0xFFFFFFFFu, lg[e], off);

    int row0 = 0, row1 = 0;
    if (lane == 0) {
#pragma unroll
        for (int e = 0; e < NE; e++) lg[e] += bg[e];
        int i0 = 0;
#pragma unroll
        for (int e = 1; e < NE; e++) if (lg[e] > lg[i0]) i0 = e;
        int i1 = (i0 == 0) ? 1 : 0;
#pragma unroll
        for (int e = 0; e < NE; e++)
            if (e != i0 && lg[e] > lg[i1]) i1 = e;
        float g0 = 1.0f / (1.0f + expf(lg[i1] - lg[i0]));
        float g1 = 1.0f - g0;
        int pos0 = atomicAdd(&g_ctrl[i0], 1);
        int pos1 = atomicAdd(&g_ctrl[i1], 1);
        row0 = i0 * CAP + pos0;
        row1 = i1 * CAP + pos1;
        g_row_tok[row0]  = t;  g_row_gate[row0] = g0;
        g_row_tok[row1]  = t;  g_row_gate[row1] = g1;
    }
    row0 = __shfl_sync(0xFFFFFFFFu, row0, 0);
    row1 = __shfl_sync(0xFFFFFFFFu, row1, 0);

    // convert this token's x row once (L1-hot), store to both g_xg rows
    const float4* xr4 = reinterpret_cast<const float4*>(xr);
#pragma unroll
    for (int i = 0; i < DM / 128; i++) {           // 4 float4 per lane
        int c4 = lane + 32 * i;
        float4 v = xr4[c4];
        __half2 a = __floats2half2_rn(v.x, v.y);
        __half2 b = __floats2half2_rn(v.z, v.w);
        uint2 o;
        o.x = *reinterpret_cast<uint32_t*>(&a);
        o.y = *reinterpret_cast<uint32_t*>(&b);
        *reinterpret_cast<uint2*>(g_xg + (size_t)row0 * DM + (size_t)c4 * 4) = o;
        *reinterpret_cast<uint2*>(g_xg + (size_t)row1 * DM + (size_t)c4 * 4) = o;
    }
}

// ---------------- fp16 HMMA grouped GEMM -------------------------------------
// CTA tile 128x128, BK=32, 256 threads, warp tile 32x64, cp.async 4-stage,
// 2 CTAs/SM.  Tiles self-located from g_ctrl counts (no tile-table kernel).
// IS1=1: Y1 = relu(g_xg@W1+b1) fp16; blocks x>=MAXTILE convert W2 -> fp16
//        (hidden in FFN1's memory-pipe shadow; W2h first read next launch).
// IS1=0: out[token] += gate * (Y1@W2 + b2) via atomicAdd (fused combine).
template<int K_TOTAL, int N_TOTAL, int IS1>
__global__ __launch_bounds__(256, 2)
void moe_mma(const float* __restrict__ bias, float* __restrict__ out,
             const float* __restrict__ W2src)
{
    constexpr int NC   = K_TOTAL / 32;
    constexpr int A_SZ = 128 * 40;               // elems
    constexpr int B_SZ = 32 * 136;               // elems
    constexpr int BUF  = A_SZ + B_SZ;            // 9472 elems

    if (IS1 && blockIdx.x >= MAXTILE) {
        // W2 conversion piggyback: 512 x-values x 16 y = 8192 blocks,
        // 1 float4 per thread = exactly NE*DF*DM elements.
        int cb = (blockIdx.x - MAXTILE) * 16 + blockIdx.y;
        int idx = cb * 256 + threadIdx.x;
        cvt4(W2src + (size_t)idx * 4, g_W2h + (size_t)idx * 4);
        return;
    }

    int e, m0;
    if (!tile_lookup(blockIdx.x, e, m0)) return;
    const int seg_start = e * CAP;
    const int seg_count = g_ctrl[e];
    const int n0 = blockIdx.y * 128;

    const int tid  = threadIdx.x;
    const int lane = tid & 31;
    const int warp = tid >> 5;
    const int wm = (warp & 3) * 32;
    const int wn = (warp >> 2) * 64;

    extern __shared__ __half smraw[];
    const uint32_t sbase = (uint32_t)__cvta_generic_to_shared(smraw);

    const __half* Ap = IS1 ? g_xg : g_Y1;
    const __half* Bp = (IS1 ? g_W1h : g_W2h)
                       + (size_t)e * K_TOTAL * N_TOTAL + n0;

    uint32_t a_soff[2];
    size_t   a_gidx[2];
#pragma unroll
    for (int it = 0; it < 2; it++) {
        int u = tid + it * 256;                  // 512 int4 per A tile
        int r = m0 + (u >> 2);
        if (r >= seg_count) r = seg_count - 1;
        a_soff[it] = (uint32_t)((u >> 2) * 40 + (u & 3) * 8) * 2;
        a_gidx[it] = (size_t)(seg_start + r) * K_TOTAL + (u & 3) * 8;
    }
    uint32_t b_soff[2];
    size_t   b_gidx[2];
#pragma unroll
    for (int it = 0; it < 2; it++) {
        int v = tid + it * 256;                  // 512 int4 for B
        int bk = v >> 4, bn = (v & 15) * 8;
        b_soff[it] = (uint32_t)(A_SZ + bk * 136 + bn) * 2;
        b_gidx[it] = (size_t)bk * N_TOTAL + bn;
    }

    const uint32_t aoff = (uint32_t)((wm + (lane & 15)) * 40 + (lane >> 4) * 8);
    const uint32_t boff = (uint32_t)((((lane >> 3) & 1) * 8 + (lane & 7)) * 136
                                     + wn + (lane >> 4) * 8);

    float c[16][4];
#pragma unroll
    for (int f = 0; f < 16; f++)
#pragma unroll
        for (int q = 0; q < 4; q++) c[f][q] = 0.0f;

#define ISSUE(KC, BS) do { \
    uint32_t base_ = sbase + (uint32_t)(BS) * (BUF * 2); \
    _Pragma("unroll") \
    for (int it = 0; it < 2; it++) \
        CP16(base_ + a_soff[it], Ap + a_gidx[it] + (size_t)(KC) * 32); \
    _Pragma("unroll") \
    for (int it = 0; it < 2; it++) \
        CP16(base_ + b_soff[it], Bp + b_gidx[it] + (size_t)(KC) * 32 * N_TOTAL); \
} while (0)

#define COMPUTE(BS) do { \
    uint32_t base_ = sbase + (uint32_t)(BS) * (BUF * 2); \
    _Pragma("unroll") \
    for (int kt = 0; kt < 2; kt++) { \
        uint32_t ah[2][4]; \
        _Pragma("unroll") \
        for (int mt = 0; mt < 2; mt++) { \
            uint32_t ad = base_ + 2u * (aoff + (uint32_t)(mt * 640 + kt * 16)); \
            LDSM_X4(ah[mt], ad); \
        } \
        uint32_t bh[8][2]; \
        _Pragma("unroll") \
        for (int bt = 0; bt < 4; bt++) { \
            uint32_t bd = base_ + 2u * ((uint32_t)A_SZ + boff \
                                        + (uint32_t)(bt * 16 + kt * 16 * 136)); \
            LDSM_X4T(bh[bt * 2][0], bh[bt * 2][1], bh[bt * 2 + 1][0], bh[bt * 2 + 1][1], bd); \
        } \
        _Pragma("unroll") \
        for (int mt = 0; mt < 2; mt++) { \
            _Pragma("unroll") \
            for (int nt = 0; nt < 8; nt++) \
                MMA_F16(c[mt * 8 + nt], ah[mt], bh[nt]); \
        } \
    } \
} while (0)

    // ---- 4-stage cp.async pipeline ----
    ISSUE(0, 0); CP_COMMIT();
    ISSUE(1, 1); CP_COMMIT();
    ISSUE(2, 2); CP_COMMIT();
    for (int kc = 0; kc < NC; kc++) {
        if (kc < NC - 2)       { CP_WAIT(2); }
        else if (kc == NC - 2) { CP_WAIT(1); }
        else                   { CP_WAIT(0); }
        __syncthreads();
        if (kc + 3 < NC) { ISSUE(kc + 3, (kc + 3) & 3); CP_COMMIT(); }
        COMPUTE(kc & 3);
    }

#undef ISSUE
#undef COMPUTE

    // ---- epilogue ----
    const float* bp = bias + (size_t)e * N_TOTAL + n0;
    const int rbase = m0 + wm + (lane >> 2);
#pragma unroll
    for (int mt = 0; mt < 2; mt++) {
#pragma unroll
        for (int nt = 0; nt < 8; nt++) {
            float* cc = c[mt * 8 + nt];
            int col = wn + nt * 8 + 2 * (lane & 3);
            float2 bb = *reinterpret_cast<const float2*>(bp + col);
#pragma unroll
            for (int h = 0; h < 2; h++) {
                int r = rbase + mt * 16 + h * 8;
                if (r < seg_count) {
                    float v0 = cc[h * 2 + 0] + bb.x;
                    float v1 = cc[h * 2 + 1] + bb.y;
                    if (IS1) {
                        v0 = fmaxf(v0, 0.0f);
                        v1 = fmaxf(v1, 0.0f);
                        __half2 hv = __floats2half2_rn(v0, v1);
                        size_t off = (size_t)(seg_start + r) * DF + n0 + col;
                        *reinterpret_cast<uint32_t*>(g_Y1 + off) =
                            *reinterpret_cast<uint32_t*>(&hv);
                    } else {
                        int grow = seg_start + r;
                        int tok  = g_row_tok[grow];
                        float gg = g_row_gate[grow];
                        float* po = out + (size_t)tok * DM + n0 + col;
                        atomicAdd(po,     gg * v0);
                        atomicAdd(po + 1, gg * v1);
                    }
                }
            }
        }
    }
}

// ---------------- launch ------------------------------------------------------
extern "C" void kernel_launch(void* const* d_in, const int* in_sizes, int n_in,
                              void* d_out, int out_size) {
    const float* x  = (const float*)d_in[0];
    const float* Wg = (const float*)d_in[1];
    const float* bg = (const float*)d_in[2];
    const float* W1 = (const float*)d_in[3];
    const float* b1 = (const float*)d_in[4];
    const float* W2 = (const float*)d_in[5];
    const float* b2 = (const float*)d_in[6];
    float* out = (float*)d_out;

    constexpr int SMEM = 4 * (128 * 40 + 32 * 136) * 2;   // 75776
    cudaFuncSetAttribute(moe_mma<DM, DF, 1>,
                         cudaFuncAttributeMaxDynamicSharedMemorySize, SMEM);
    cudaFuncSetAttribute(moe_mma<DF, DM, 0>,
                         cudaFuncAttributeMaxDynamicSharedMemorySize, SMEM);

    void* p_ctrl;
    cudaGetSymbolAddress(&p_ctrl, g_ctrl);
    cudaMemsetAsync(p_ctrl, 0, NE * sizeof(int));

    gatecvt_kernel<<<GATE_BLKS + CVT1_BLKS, 256>>>(x, Wg, bg, W1, out);

    dim3 grid1(MAXTILE + 512, DF / 128);   // tiles + W2-convert piggyback
    moe_mma<DM, DF, 1><<<grid1, 256, SMEM>>>(b1, out, W2);

    dim3 grid2(MAXTILE, DM / 128);         // fused combine epilogue
    moe_mma<DF, DM, 0><<<grid2, 256, SMEM>>>(b2, out, W2);
}

// round 15
// speedup vs baseline: 1.0814x; 1.0814x over previous
#include <cuda_runtime.h>
#include <cuda_fp16.h>
#include <cstdint>

#define T_TOKENS 4096
#define DM 512
#define NE 8
#define DF 2048
#define NPAIRS (T_TOKENS * 2)
#define CAP 8192      // fixed per-expert segment capacity
#define MAXTILE 72    // grid upper bound for M=128 tiles

// ---------------- device scratch ------------------------------------------
__device__ int   g_ctrl[NE];                      // per-expert pair counts
__device__ int   g_row_tok[NE * CAP];
__device__ float g_row_gate[NE * CAP];
__device__ __half g_xg[(size_t)NE * CAP * DM];    // 64 MiB fixed-base gathered x
__device__ __half g_Y1[(size_t)NE * CAP * DF];    // 256 MiB fixed-base Y1
__device__ __half g_W1h[(size_t)NE * DM * DF];    // 16 MiB
__device__ __half g_W2h[(size_t)NE * DF * DM];    // 16 MiB

// ---------------- helpers ----------------------------------------------------
#define LDSM_X4(R, ADDR) \
    asm volatile("ldmatrix.sync.aligned.m8n8.x4.shared.b16 {%0,%1,%2,%3}, [%4];" \
        : "=r"((R)[0]), "=r"((R)[1]), "=r"((R)[2]), "=r"((R)[3]) : "r"(ADDR))

#define LDSM_X4T(R0, R1, R2, R3, ADDR) \
    asm volatile("ldmatrix.sync.aligned.m8n8.x4.trans.shared.b16 {%0,%1,%2,%3}, [%4];" \
        : "=r"(R0), "=r"(R1), "=r"(R2), "=r"(R3) : "r"(ADDR))

#define MMA_F16(C, A, B) \
    asm volatile("mma.sync.aligned.m16n8k16.row.col.f32.f16.f16.f32 " \
        "{%0,%1,%2,%3}, {%4,%5,%6,%7}, {%8,%9}, {%0,%1,%2,%3};" \
        : "+f"((C)[0]), "+f"((C)[1]), "+f"((C)[2]), "+f"((C)[3]) \
        : "r"((A)[0]), "r"((A)[1]), "r"((A)[2]), "r"((A)[3]), \
          "r"((B)[0]), "r"((B)[1]))

#define CP16(DST, SRC) \
    asm volatile("cp.async.cg.shared.global [%0], [%1], 16;" \
        :: "r"(DST), "l"(SRC))
#define CP_COMMIT() asm volatile("cp.async.commit_group;")
#define CP_WAIT(N)  asm volatile("cp.async.wait_group %0;" :: "n"(N))

__device__ __forceinline__ void cvt4(const float* srcp, __half* dst) {
    float4 v = *reinterpret_cast<const float4*>(srcp);
    __half2 a = __floats2half2_rn(v.x, v.y);
    __half2 b = __floats2half2_rn(v.z, v.w);
    uint2 o;
    o.x = *reinterpret_cast<uint32_t*>(&a);
    o.y = *reinterpret_cast<uint32_t*>(&b);
    *reinterpret_cast<uint2*>(dst) = o;
}

// locate M=128 tile for linear tile id bx; returns false if beyond last tile
__device__ __forceinline__ bool tile_lookup(int bx, int& e, int& m0) {
#pragma unroll
    for (int ee = 0; ee < NE; ee++) {
        int nt = (g_ctrl[ee] + 127) >> 7;
        if (bx < nt) { e = ee; m0 = bx << 7; return true; }
        bx -= nt;
    }
    return false;
}

// ---------------- gate+slot+gather (blocks 0..511) + W1/W2 convert ----------
// Convert blocks: 4 float4 per thread (high MLP, BW-bound).
#define GATE_BLKS 512
#define NW4 (NE * DM * DF / 4)                     // float4 per weight tensor
#define CVT_BLKS ((2 * NW4) / 1024)                // 4096

__global__ __launch_bounds__(256)
void gatecvt_kernel(const float* __restrict__ x,
                    const float* __restrict__ Wg,
                    const float* __restrict__ bg,
                    const float* __restrict__ W1,
                    const float* __restrict__ W2,
                    float* __restrict__ out) {
    const int bid = blockIdx.x;
    if (bid >= GATE_BLKS) {
        size_t base = (size_t)(bid - GATE_BLKS) * 1024 + threadIdx.x;
#pragma unroll
        for (int k = 0; k < 4; k++) {
            size_t idx = base + k * 256;
            if (idx < NW4) cvt4(W1 + idx * 4, g_W1h + idx * 4);
            else           cvt4(W2 + (idx - NW4) * 4, g_W2h + (idx - NW4) * 4);
        }
        return;
    }

    // zero this block's 8 output token rows (1024 float4)
    {
        float4 z; z.x = z.y = z.z = z.w = 0.0f;
        float4* ob = reinterpret_cast<float4*>(out) + (size_t)bid * 1024;
#pragma unroll
        for (int i = 0; i < 4; i++) ob[threadIdx.x + 256 * i] = z;
    }

    __shared__ float sWgT[NE * DM];   // transposed [e][d]
    for (int i = threadIdx.x; i < DM * NE; i += blockDim.x) {
        int d = i >> 3, e = i & 7;
        sWgT[e * DM + d] = Wg[i];
    }
    __syncthreads();

    int warp = threadIdx.x >> 5, lane = threadIdx.x & 31;
    int t = bid * 8 + warp;
    const float* xr = x + (size_t)t * DM;

    float lg[NE];
#pragma unroll
    for (int e = 0; e < NE; e++) lg[e] = 0.0f;
#pragma unroll
    for (int i = 0; i < DM / 32; i++) {
        int d = lane + 32 * i;
        float xv = xr[d];
#pragma unroll
        for (int e = 0; e < NE; e++)
            lg[e] = fmaf(xv, sWgT[e * DM + d], lg[e]);
    }
#pragma unroll
    for (int off = 16; off > 0; off >>= 1)
#pragma unroll
        for (int e = 0; e < NE; e++)
            lg[e] += __shfl_xor_sync(0xFFFFFFFFu, lg[e], off);

    int row0 = 0, row1 = 0;
    if (lane == 0) {
#pragma unroll
        for (int e = 0; e < NE; e++) lg[e] += bg[e];
        int i0 = 0;
#pragma unroll
        for (int e = 1; e < NE; e++) if (lg[e] > lg[i0]) i0 = e;
        int i1 = (i0 == 0) ? 1 : 0;
#pragma unroll
        for (int e = 0; e < NE; e++)
            if (e != i0 && lg[e] > lg[i1]) i1 = e;
        float g0 = 1.0f / (1.0f + expf(lg[i1] - lg[i0]));
        float g1 = 1.0f - g0;
        int pos0 = atomicAdd(&g_ctrl[i0], 1);
        int pos1 = atomicAdd(&g_ctrl[i1], 1);
        row0 = i0 * CAP + pos0;
        row1 = i1 * CAP + pos1;
        g_row_tok[row0]  = t;  g_row_gate[row0] = g0;
        g_row_tok[row1]  = t;  g_row_gate[row1] = g1;
    }
    row0 = __shfl_sync(0xFFFFFFFFu, row0, 0);
    row1 = __shfl_sync(0xFFFFFFFFu, row1, 0);

    // convert this token's x row once (L1-hot), store to both g_xg rows
    const float4* xr4 = reinterpret_cast<const float4*>(xr);
#pragma unroll
    for (int i = 0; i < DM / 128; i++) {           // 4 float4 per lane
        int c4 = lane + 32 * i;
        float4 v = xr4[c4];
        __half2 a = __floats2half2_rn(v.x, v.y);
        __half2 b = __floats2half2_rn(v.z, v.w);
        uint2 o;
        o.x = *reinterpret_cast<uint32_t*>(&a);
        o.y = *reinterpret_cast<uint32_t*>(&b);
        *reinterpret_cast<uint2*>(g_xg + (size_t)row0 * DM + (size_t)c4 * 4) = o;
        *reinterpret_cast<uint2*>(g_xg + (size_t)row1 * DM + (size_t)c4 * 4) = o;
    }
}

// ---------------- fp16 HMMA grouped GEMM -------------------------------------
// CTA tile 128x128, BK=32, 256 threads, warp tile 32x64, cp.async 4-stage,
// 2 CTAs/SM.  Fixed-base segments, tile self-lookup from g_ctrl.
// IS1=1: Y1 = relu(g_xg@W1+b1) fp16.
// IS1=0: out[token] += gate * (Y1@W2 + b2) via atomicAdd (fused combine).
template<int K_TOTAL, int N_TOTAL, int IS1>
__global__ __launch_bounds__(256, 2)
void moe_mma(const float* __restrict__ bias, float* __restrict__ out)
{
    constexpr int NC   = K_TOTAL / 32;
    constexpr int A_SZ = 128 * 40;               // elems
    constexpr int B_SZ = 32 * 136;               // elems
    constexpr int BUF  = A_SZ + B_SZ;            // 9472 elems

    int e, m0;
    if (!tile_lookup(blockIdx.x, e, m0)) return;
    const int seg_start = e * CAP;
    const int seg_count = g_ctrl[e];
    const int n0 = blockIdx.y * 128;

    const int tid  = threadIdx.x;
    const int lane = tid & 31;
    const int warp = tid >> 5;
    const int wm = (warp & 3) * 32;
    const int wn = (warp >> 2) * 64;

    extern __shared__ __half smraw[];
    const uint32_t sbase = (uint32_t)__cvta_generic_to_shared(smraw);

    const __half* Ap = IS1 ? g_xg : g_Y1;
    const __half* Bp = (IS1 ? g_W1h : g_W2h)
                       + (size_t)e * K_TOTAL * N_TOTAL + n0;

    uint32_t a_soff[2];
    size_t   a_gidx[2];
#pragma unroll
    for (int it = 0; it < 2; it++) {
        int u = tid + it * 256;                  // 512 int4 per A tile
        int r = m0 + (u >> 2);
        if (r >= seg_count) r = seg_count - 1;
        a_soff[it] = (uint32_t)((u >> 2) * 40 + (u & 3) * 8) * 2;
        a_gidx[it] = (size_t)(seg_start + r) * K_TOTAL + (u & 3) * 8;
    }
    uint32_t b_soff[2];
    size_t   b_gidx[2];
#pragma unroll
    for (int it = 0; it < 2; it++) {
        int v = tid + it * 256;                  // 512 int4 for B
        int bk = v >> 4, bn = (v & 15) * 8;
        b_soff[it] = (uint32_t)(A_SZ + bk * 136 + bn) * 2;
        b_gidx[it] = (size_t)bk * N_TOTAL + bn;
    }

    const uint32_t aoff = (uint32_t)((wm + (lane & 15)) * 40 + (lane >> 4) * 8);
    const uint32_t boff = (uint32_t)((((lane >> 3) & 1) * 8 + (lane & 7)) * 136
                                     + wn + (lane >> 4) * 8);

    float c[16][4];
#pragma unroll
    for (int f = 0; f < 16; f++)
#pragma unroll
        for (int q = 0; q < 4; q++) c[f][q] = 0.0f;

#define ISSUE(KC, BS) do { \
    uint32_t base_ = sbase + (uint32_t)(BS) * (BUF * 2); \
    _Pragma("unroll") \
    for (int it = 0; it < 2; it++) \
        CP16(base_ + a_soff[it], Ap + a_gidx[it] + (size_t)(KC) * 32); \
    _Pragma("unroll") \
    for (int it = 0; it < 2; it++) \
        CP16(base_ + b_soff[it], Bp + b_gidx[it] + (size_t)(KC) * 32 * N_TOTAL); \
} while (0)

#define COMPUTE(BS) do { \
    uint32_t base_ = sbase + (uint32_t)(BS) * (BUF * 2); \
    _Pragma("unroll") \
    for (int kt = 0; kt < 2; kt++) { \
        uint32_t ah[2][4]; \
        _Pragma("unroll") \
        for (int mt = 0; mt < 2; mt++) { \
            uint32_t ad = base_ + 2u * (aoff + (uint32_t)(mt * 640 + kt * 16)); \
            LDSM_X4(ah[mt], ad); \
        } \
        uint32_t bh[8][2]; \
        _Pragma("unroll") \
        for (int bt = 0; bt < 4; bt++) { \
            uint32_t bd = base_ + 2u * ((uint32_t)A_SZ + boff \
                                        + (uint32_t)(bt * 16 + kt * 16 * 136)); \
            LDSM_X4T(bh[bt * 2][0], bh[bt * 2][1], bh[bt * 2 + 1][0], bh[bt * 2 + 1][1], bd); \
        } \
        _Pragma("unroll") \
        for (int mt = 0; mt < 2; mt++) { \
            _Pragma("unroll") \
            for (int nt = 0; nt < 8; nt++) \
                MMA_F16(c[mt * 8 + nt], ah[mt], bh[nt]); \
        } \
    } \
} while (0)

    // ---- 4-stage cp.async pipeline ----
    ISSUE(0, 0); CP_COMMIT();
    ISSUE(1, 1); CP_COMMIT();
    ISSUE(2, 2); CP_COMMIT();
    for (int kc = 0; kc < NC; kc++) {
        if (kc < NC - 2)       { CP_WAIT(2); }
        else if (kc == NC - 2) { CP_WAIT(1); }
        else                   { CP_WAIT(0); }
        __syncthreads();
        if (kc + 3 < NC) { ISSUE(kc + 3, (kc + 3) & 3); CP_COMMIT(); }
        COMPUTE(kc & 3);
    }

#undef ISSUE
#undef COMPUTE

    // ---- epilogue ----
    const float* bp = bias + (size_t)e * N_TOTAL + n0;
    const int rbase = m0 + wm + (lane >> 2);
#pragma unroll
    for (int mt = 0; mt < 2; mt++) {
#pragma unroll
        for (int nt = 0; nt < 8; nt++) {
            float* cc = c[mt * 8 + nt];
            int col = wn + nt * 8 + 2 * (lane & 3);
            float2 bb = *reinterpret_cast<const float2*>(bp + col);
#pragma unroll
            for (int h = 0; h < 2; h++) {
                int r = rbase + mt * 16 + h * 8;
                if (r < seg_count) {
                    float v0 = cc[h * 2 + 0] + bb.x;
                    float v1 = cc[h * 2 + 1] + bb.y;
                    if (IS1) {
                        v0 = fmaxf(v0, 0.0f);
                        v1 = fmaxf(v1, 0.0f);
                        __half2 hv = __floats2half2_rn(v0, v1);
                        size_t off = (size_t)(seg_start + r) * DF + n0 + col;
                        *reinterpret_cast<uint32_t*>(g_Y1 + off) =
                            *reinterpret_cast<uint32_t*>(&hv);
                    } else {
                        int grow = seg_start + r;
                        int tok  = g_row_tok[grow];
                        float gg = g_row_gate[grow];
                        float* po = out + (size_t)tok * DM + n0 + col;
                        atomicAdd(po,     gg * v0);
                        atomicAdd(po + 1, gg * v1);
                    }
                }
            }
        }
    }
}

// ---------------- launch ------------------------------------------------------
extern "C" void kernel_launch(void* const* d_in, const int* in_sizes, int n_in,
                              void* d_out, int out_size) {
    const float* x  = (const float*)d_in[0];
    const float* Wg = (const float*)d_in[1];
    const float* bg = (const float*)d_in[2];
    const float* W1 = (const float*)d_in[3];
    const float* b1 = (const float*)d_in[4];
    const float* W2 = (const float*)d_in[5];
    const float* b2 = (const float*)d_in[6];
    float* out = (float*)d_out;

    constexpr int SMEM = 4 * (128 * 40 + 32 * 136) * 2;   // 75776
    cudaFuncSetAttribute(moe_mma<DM, DF, 1>,
                         cudaFuncAttributeMaxDynamicSharedMemorySize, SMEM);
    cudaFuncSetAttribute(moe_mma<DF, DM, 0>,
                         cudaFuncAttributeMaxDynamicSharedMemorySize, SMEM);

    void* p_ctrl;
    cudaGetSymbolAddress(&p_ctrl, g_ctrl);
    cudaMemsetAsync(p_ctrl, 0, NE * sizeof(int));

    gatecvt_kernel<<<GATE_BLKS + CVT_BLKS, 256>>>(x, Wg, bg, W1, W2, out);

    dim3 grid1(MAXTILE, DF / 128);   // tile self-lookup, M=128
    moe_mma<DM, DF, 1><<<grid1, 256, SMEM>>>(b1, out);

    dim3 grid2(MAXTILE, DM / 128);   // fused combine epilogue
    moe_mma<DF, DM, 0><<<grid2, 256, SMEM>>>(b2, out);
}

// round 16
// speedup vs baseline: 1.0931x; 1.0108x over previous
#include <cuda_runtime.h>
#include <cuda_fp16.h>
#include <cstdint>

#define T_TOKENS 4096
#define DM 512
#define NE 8
#define DF 2048
#define NPAIRS (T_TOKENS * 2)
#define CAP 8192      // fixed per-expert segment capacity
#define MAXTILE 72    // grid upper bound for M=128 tiles

// ---------------- device scratch ------------------------------------------
__device__ int   g_ctrl[NE];                      // per-expert pair counts
__device__ int   g_row_tok[NE * CAP];
__device__ float g_row_gate[NE * CAP];
__device__ __half g_xg[(size_t)NE * CAP * DM];    // 64 MiB fixed-base gathered x
__device__ __half g_Y1[(size_t)NE * CAP * DF];    // 256 MiB fixed-base Y1
__device__ __half g_W1h[(size_t)NE * DM * DF];    // 16 MiB
__device__ __half g_W2h[(size_t)NE * DF * DM];    // 16 MiB

// ---------------- helpers ----------------------------------------------------
#define LDSM_X4(R, ADDR) \
    asm volatile("ldmatrix.sync.aligned.m8n8.x4.shared.b16 {%0,%1,%2,%3}, [%4];" \
        : "=r"((R)[0]), "=r"((R)[1]), "=r"((R)[2]), "=r"((R)[3]) : "r"(ADDR))

#define LDSM_X4T(R0, R1, R2, R3, ADDR) \
    asm volatile("ldmatrix.sync.aligned.m8n8.x4.trans.shared.b16 {%0,%1,%2,%3}, [%4];" \
        : "=r"(R0), "=r"(R1), "=r"(R2), "=r"(R3) : "r"(ADDR))

#define MMA_F16(C, A, B) \
    asm volatile("mma.sync.aligned.m16n8k16.row.col.f32.f16.f16.f32 " \
        "{%0,%1,%2,%3}, {%4,%5,%6,%7}, {%8,%9}, {%0,%1,%2,%3};" \
        : "+f"((C)[0]), "+f"((C)[1]), "+f"((C)[2]), "+f"((C)[3]) \
        : "r"((A)[0]), "r"((A)[1]), "r"((A)[2]), "r"((A)[3]), \
          "r"((B)[0]), "r"((B)[1]))

#define CP16(DST, SRC) \
    asm volatile("cp.async.cg.shared.global [%0], [%1], 16;" \
        :: "r"(DST), "l"(SRC))
#define CP_COMMIT() asm volatile("cp.async.commit_group;")
#define CP_WAIT(N)  asm volatile("cp.async.wait_group %0;" :: "n"(N))

// convert 2 consecutive float4 (8 fp32) -> one uint4 (8 fp16), 16B store
__device__ __forceinline__ void cvt8(const float4* s, __half* dst) {
    float4 v0 = s[0];
    float4 v1 = s[1];
    __half2 a = __floats2half2_rn(v0.x, v0.y);
    __half2 b = __floats2half2_rn(v0.z, v0.w);
    __half2 c = __floats2half2_rn(v1.x, v1.y);
    __half2 d = __floats2half2_rn(v1.z, v1.w);
    uint4 o;
    o.x = *reinterpret_cast<uint32_t*>(&a);
    o.y = *reinterpret_cast<uint32_t*>(&b);
    o.z = *reinterpret_cast<uint32_t*>(&c);
    o.w = *reinterpret_cast<uint32_t*>(&d);
    *reinterpret_cast<uint4*>(dst) = o;
}

// locate M=128 tile for linear tile id bx; returns false if beyond last tile
__device__ __forceinline__ bool tile_lookup(int bx, int& e, int& m0) {
#pragma unroll
    for (int ee = 0; ee < NE; ee++) {
        int nt = (g_ctrl[ee] + 127) >> 7;
        if (bx < nt) { e = ee; m0 = bx << 7; return true; }
        bx -= nt;
    }
    return false;
}

// ---------------- gate+slot+gather (blocks 0..511) + W1/W2 convert ----------
#define GATE_BLKS 512
#define NW4 (NE * DM * DF / 4)                     // float4 per weight tensor
#define CVT_BLKS ((2 * NW4) / 1024)                // 4096

__global__ __launch_bounds__(256)
void gatecvt_kernel(const float* __restrict__ x,
                    const float* __restrict__ Wg,
                    const float* __restrict__ bg,
                    const float* __restrict__ W1,
                    const float* __restrict__ W2,
                    float* __restrict__ out) {
    const int bid = blockIdx.x;
    if (bid >= GATE_BLKS) {
        // 2 iterations x 2 float4 per thread = 1024 f4 per block, 16B stores
        size_t base = (size_t)(bid - GATE_BLKS) * 1024;
#pragma unroll
        for (int k = 0; k < 2; k++) {
            size_t j = base + k * 512 + (size_t)threadIdx.x * 2;   // even f4 idx
            if (j < NW4)
                cvt8(reinterpret_cast<const float4*>(W1) + j, g_W1h + j * 4);
            else
                cvt8(reinterpret_cast<const float4*>(W2) + (j - NW4),
                     g_W2h + (j - NW4) * 4);
        }
        return;
    }

    // zero this block's 8 output token rows (1024 float4)
    {
        float4 z; z.x = z.y = z.z = z.w = 0.0f;
        float4* ob = reinterpret_cast<float4*>(out) + (size_t)bid * 1024;
#pragma unroll
        for (int i = 0; i < 4; i++) ob[threadIdx.x + 256 * i] = z;
    }

    __shared__ float sWgT[NE * DM];   // transposed [e][d]
    for (int i = threadIdx.x; i < DM * NE; i += blockDim.x) {
        int d = i >> 3, e = i & 7;
        sWgT[e * DM + d] = Wg[i];
    }
    __syncthreads();

    int warp = threadIdx.x >> 5, lane = threadIdx.x & 31;
    int t = bid * 8 + warp;
    const float* xr = x + (size_t)t * DM;

    float lg[NE];
#pragma unroll
    for (int e = 0; e < NE; e++) lg[e] = 0.0f;
#pragma unroll
    for (int i = 0; i < DM / 32; i++) {
        int d = lane + 32 * i;
        float xv = xr[d];
#pragma unroll
        for (int e = 0; e < NE; e++)
            lg[e] = fmaf(xv, sWgT[e * DM + d], lg[e]);
    }
#pragma unroll
    for (int off = 16; off > 0; off >>= 1)
#pragma unroll
        for (int e = 0; e < NE; e++)
            lg[e] += __shfl_xor_sync(0xFFFFFFFFu, lg[e], off);

    int row0 = 0, row1 = 0;
    if (lane == 0) {
#pragma unroll
        for (int e = 0; e < NE; e++) lg[e] += bg[e];
        int i0 = 0;
#pragma unroll
        for (int e = 1; e < NE; e++) if (lg[e] > lg[i0]) i0 = e;
        int i1 = (i0 == 0) ? 1 : 0;
#pragma unroll
        for (int e = 0; e < NE; e++)
            if (e != i0 && lg[e] > lg[i1]) i1 = e;
        float g0 = 1.0f / (1.0f + expf(lg[i1] - lg[i0]));
        float g1 = 1.0f - g0;
        int pos0 = atomicAdd(&g_ctrl[i0], 1);
        int pos1 = atomicAdd(&g_ctrl[i1], 1);
        row0 = i0 * CAP + pos0;
        row1 = i1 * CAP + pos1;
        g_row_tok[row0]  = t;  g_row_gate[row0] = g0;
        g_row_tok[row1]  = t;  g_row_gate[row1] = g1;
    }
    row0 = __shfl_sync(0xFFFFFFFFu, row0, 0);
    row1 = __shfl_sync(0xFFFFFFFFu, row1, 0);

    // convert token's x row (L1-hot), 16B stores to both g_xg rows
    const float4* xr4 = reinterpret_cast<const float4*>(xr);
#pragma unroll
    for (int i = 0; i < 2; i++) {                  // 2 x (2 float4) per lane
        int j = i * 64 + lane * 2;                 // even f4 idx within row
        float4 v0 = xr4[j], v1 = xr4[j + 1];
        __half2 a = __floats2half2_rn(v0.x, v0.y);
        __half2 b = __floats2half2_rn(v0.z, v0.w);
        __half2 c = __floats2half2_rn(v1.x, v1.y);
        __half2 d = __floats2half2_rn(v1.z, v1.w);
        uint4 o;
        o.x = *reinterpret_cast<uint32_t*>(&a);
        o.y = *reinterpret_cast<uint32_t*>(&b);
        o.z = *reinterpret_cast<uint32_t*>(&c);
        o.w = *reinterpret_cast<uint32_t*>(&d);
        *reinterpret_cast<uint4*>(g_xg + (size_t)row0 * DM + (size_t)j * 4) = o;
        *reinterpret_cast<uint4*>(g_xg + (size_t)row1 * DM + (size_t)j * 4) = o;
    }
}

// ---------------- fp16 HMMA grouped GEMM -------------------------------------
// CTA tile 128x128, BK=32, 256 threads, warp tile 32x64, cp.async 4-stage,
// 2 CTAs/SM.  Fixed-base segments, tile self-lookup from g_ctrl.
// IS1=1: Y1 = relu(g_xg@W1+b1) fp16.
// IS1=0: out[token] += gate * (Y1@W2 + b2) via atomicAdd (fused combine).
template<int K_TOTAL, int N_TOTAL, int IS1>
__global__ __launch_bounds__(256, 2)
void moe_mma(const float* __restrict__ bias, float* __restrict__ out)
{
    constexpr int NC   = K_TOTAL / 32;
    constexpr int A_SZ = 128 * 40;               // elems
    constexpr int B_SZ = 32 * 136;               // elems
    constexpr int BUF  = A_SZ + B_SZ;            // 9472 elems

    int e, m0;
    if (!tile_lookup(blockIdx.x, e, m0)) return;
    const int seg_start = e * CAP;
    const int seg_count = g_ctrl[e];
    const int n0 = blockIdx.y * 128;

    const int tid  = threadIdx.x;
    const int lane = tid & 31;
    const int warp = tid >> 5;
    const int wm = (warp & 3) * 32;
    const int wn = (warp >> 2) * 64;

    extern __shared__ __half smraw[];
    const uint32_t sbase = (uint32_t)__cvta_generic_to_shared(smraw);

    const __half* Ap = IS1 ? g_xg : g_Y1;
    const __half* Bp = (IS1 ? g_W1h : g_W2h)
                       + (size_t)e * K_TOTAL * N_TOTAL + n0;

    uint32_t a_soff[2];
    size_t   a_gidx[2];
#pragma unroll
    for (int it = 0; it < 2; it++) {
        int u = tid + it * 256;                  // 512 int4 per A tile
        int r = m0 + (u >> 2);
        if (r >= seg_count) r = seg_count - 1;
        a_soff[it] = (uint32_t)((u >> 2) * 40 + (u & 3) * 8) * 2;
        a_gidx[it] = (size_t)(seg_start + r) * K_TOTAL + (u & 3) * 8;
    }
    uint32_t b_soff[2];
    size_t   b_gidx[2];
#pragma unroll
    for (int it = 0; it < 2; it++) {
        int v = tid + it * 256;                  // 512 int4 for B
        int bk = v >> 4, bn = (v & 15) * 8;
        b_soff[it] = (uint32_t)(A_SZ + bk * 136 + bn) * 2;
        b_gidx[it] = (size_t)bk * N_TOTAL + bn;
    }

    const uint32_t aoff = (uint32_t)((wm + (lane & 15)) * 40 + (lane >> 4) * 8);
    const uint32_t boff = (uint32_t)((((lane >> 3) & 1) * 8 + (lane & 7)) * 136
                                     + wn + (lane >> 4) * 8);

    float c[16][4];
#pragma unroll
    for (int f = 0; f < 16; f++)
#pragma unroll
        for (int q = 0; q < 4; q++) c[f][q] = 0.0f;

#define ISSUE(KC, BS) do { \
    uint32_t base_ = sbase + (uint32_t)(BS) * (BUF * 2); \
    _Pragma("unroll") \
    for (int it = 0; it < 2; it++) \
        CP16(base_ + a_soff[it], Ap + a_gidx[it] + (size_t)(KC) * 32); \
    _Pragma("unroll") \
    for (int it = 0; it < 2; it++) \
        CP16(base_ + b_soff[it], Bp + b_gidx[it] + (size_t)(KC) * 32 * N_TOTAL); \
} while (0)

#define COMPUTE(BS) do { \
    uint32_t base_ = sbase + (uint32_t)(BS) * (BUF * 2); \
    _Pragma("unroll") \
    for (int kt = 0; kt < 2; kt++) { \
        uint32_t ah[2][4]; \
        _Pragma("unroll") \
        for (int mt = 0; mt < 2; mt++) { \
            uint32_t ad = base_ + 2u * (aoff + (uint32_t)(mt * 640 + kt * 16)); \
            LDSM_X4(ah[mt], ad); \
        } \
        uint32_t bh[8][2]; \
        _Pragma("unroll") \
        for (int bt = 0; bt < 4; bt++) { \
            uint32_t bd = base_ + 2u * ((uint32_t)A_SZ + boff \
                                        + (uint32_t)(bt * 16 + kt * 16 * 136)); \
            LDSM_X4T(bh[bt * 2][0], bh[bt * 2][1], bh[bt * 2 + 1][0], bh[bt * 2 + 1][1], bd); \
        } \
        _Pragma("unroll") \
        for (int mt = 0; mt < 2; mt++) { \
            _Pragma("unroll") \
            for (int nt = 0; nt < 8; nt++) \
                MMA_F16(c[mt * 8 + nt], ah[mt], bh[nt]); \
        } \
    } \
} while (0)

    // ---- 4-stage cp.async pipeline ----
    ISSUE(0, 0); CP_COMMIT();
    ISSUE(1, 1); CP_COMMIT();
    ISSUE(2, 2); CP_COMMIT();
    for (int kc = 0; kc < NC; kc++) {
        if (kc < NC - 2)       { CP_WAIT(2); }
        else if (kc == NC - 2) { CP_WAIT(1); }
        else                   { CP_WAIT(0); }
        __syncthreads();
        if (kc + 3 < NC) { ISSUE(kc + 3, (kc + 3) & 3); CP_COMMIT(); }
        COMPUTE(kc & 3);
    }

#undef ISSUE
#undef COMPUTE

    // ---- epilogue ----
    const float* bp = bias + (size_t)e * N_TOTAL + n0;
    const int rbase = m0 + wm + (lane >> 2);
#pragma unroll
    for (int mt = 0; mt < 2; mt++) {
#pragma unroll
        for (int nt = 0; nt < 8; nt++) {
            float* cc = c[mt * 8 + nt];
            int col = wn + nt * 8 + 2 * (lane & 3);
            float2 bb = *reinterpret_cast<const float2*>(bp + col);
#pragma unroll
            for (int h = 0; h < 2; h++) {
                int r = rbase + mt * 16 + h * 8;
                if (r < seg_count) {
                    float v0 = cc[h * 2 + 0] + bb.x;
                    float v1 = cc[h * 2 + 1] + bb.y;
                    if (IS1) {
                        v0 = fmaxf(v0, 0.0f);
                        v1 = fmaxf(v1, 0.0f);
                        __half2 hv = __floats2half2_rn(v0, v1);
                        size_t off = (size_t)(seg_start + r) * DF + n0 + col;
                        *reinterpret_cast<uint32_t*>(g_Y1 + off) =
                            *reinterpret_cast<uint32_t*>(&hv);
                    } else {
                        int grow = seg_start + r;
                        int tok  = g_row_tok[grow];
                        float gg = g_row_gate[grow];
                        float* po = out + (size_t)tok * DM + n0 + col;
                        atomicAdd(po,     gg * v0);
                        atomicAdd(po + 1, gg * v1);
                    }
                }
            }
        }
    }
}

// ---------------- launch ------------------------------------------------------
extern "C" void kernel_launch(void* const* d_in, const int* in_sizes, int n_in,
                              void* d_out, int out_size) {
    const float* x  = (const float*)d_in[0];
    const float* Wg = (const float*)d_in[1];
    const float* bg = (const float*)d_in[2];
    const float* W1 = (const float*)d_in[3];
    const float* b1 = (const float*)d_in[4];
    const float* W2 = (const float*)d_in[5];
    const float* b2 = (const float*)d_in[6];
    float* out = (float*)d_out;

    constexpr int SMEM = 4 * (128 * 40 + 32 * 136) * 2;   // 75776
    cudaFuncSetAttribute(moe_mma<DM, DF, 1>,
                         cudaFuncAttributeMaxDynamicSharedMemorySize, SMEM);
    cudaFuncSetAttribute(moe_mma<DF, DM, 0>,
                         cudaFuncAttributeMaxDynamicSharedMemorySize, SMEM);

    void* p_ctrl;
    cudaGetSymbolAddress(&p_ctrl, g_ctrl);
    cudaMemsetAsync(p_ctrl, 0, NE * sizeof(int));

    gatecvt_kernel<<<GATE_BLKS + CVT_BLKS, 256>>>(x, Wg, bg, W1, W2, out);

    dim3 grid1(MAXTILE, DF / 128);   // tile self-lookup, M=128
    moe_mma<DM, DF, 1><<<grid1, 256, SMEM>>>(b1, out);

    dim3 grid2(MAXTILE, DM / 128);   // fused combine epilogue
    moe_mma<DF, DM, 0><<<grid2, 256, SMEM>>>(b2, out);
}